// round 1
// baseline (speedup 1.0000x reference)
#include <cuda_runtime.h>
#include <math.h>

// Problem constants
#define B_  32
#define N_  512
#define L_  12
#define U_  64
#define M_  5      // diffusion terms
#define HOR 12

// ---------------------------------------------------------------------------
// Scratch: one big __device__ array, offsets in floats
// ---------------------------------------------------------------------------
#define OFF_A0  0L
#define OFF_A1  8388608L
#define OFF_P   16777216L      // (32, 4*512, 512): [A0 ; 2A0^2-I ; A1A0 ; 2A1^2A0-A0]
#define OFF_XG  50331648L      // (32, 512, 128) max
#define OFF_TG  52428800L      // (32, 2048, 128) max
#define OFF_TC  60817408L      // (32, 2048, 64)
#define OFF_RHX 65011712L      // (32, 512, 64)
#define OFF_U   66060288L      // (32, 512, 64)
#define OFF_H0  67108864L
#define OFF_H1  68157440L
#define OFF_H2  69206016L
#define OFF_H3  70254592L
#define OFF_HIS 71303168L
#define OFF_FC1 72351744L      // (16384, 256)
#define OFF_DEC 76546048L      // (16384)
#define OFF_RS0 76562432L
#define OFF_RS1 76578816L
#define SCRATCH_TOTAL 76595200L

__device__ float g_scratch[SCRATCH_TOTAL];

// ---------------------------------------------------------------------------
// Support construction
// ---------------------------------------------------------------------------
__global__ void rowsum_k(const float* __restrict__ adj, float* __restrict__ rs0) {
    int w = (blockIdx.x * blockDim.x + threadIdx.x) >> 5;   // row id: b*512+i
    int lane = threadIdx.x & 31;
    if (w >= B_ * N_) return;
    const float* base = adj + (long)w * N_;
    float s = 0.f;
    for (int j = lane; j < N_; j += 32) s += base[j];
    #pragma unroll
    for (int o = 16; o; o >>= 1) s += __shfl_xor_sync(0xffffffffu, s, o);
    if (lane == 0) rs0[w] = s + 1.0f;
}

__global__ void colsum_k(const float* __restrict__ adj, float* __restrict__ rs1) {
    int idx = blockIdx.x * blockDim.x + threadIdx.x;  // b*512+i
    if (idx >= B_ * N_) return;
    int b = idx >> 9, i = idx & 511;
    const float* base = adj + (long)b * N_ * N_ + i;
    float s = 1.0f;
    for (int j = 0; j < N_; j++) s += base[(long)j * N_];
    rs1[idx] = s;
}

__global__ void fill_supports(const float* __restrict__ adj,
                              const float* __restrict__ rs0,
                              const float* __restrict__ rs1,
                              float* __restrict__ A0, float* __restrict__ A1,
                              float* __restrict__ P) {
    long idx = (long)blockIdx.x * blockDim.x + threadIdx.x;  // over 32*512*512
    if (idx >= (long)B_ * N_ * N_) return;
    int j = (int)(idx & 511);
    long t = idx >> 9;
    int i = (int)(t & 511);
    int b = (int)(t >> 9);
    float d = (i == j) ? 1.f : 0.f;
    float a = adj[idx];
    float v0 = (a + d) / rs0[b * N_ + i];
    A0[idx] = v0;
    P[(long)b * 4 * N_ * N_ + (long)i * N_ + j] = v0;   // block m=1: A0
    float at = adj[((long)b * N_ + j) * N_ + i];
    A1[idx] = (at + d) / rs1[b * N_ + i];
}

// ---------------------------------------------------------------------------
// Generic batched SGEMM: C[b] = A[b] @ Bm[b]  (row-major), tile 128x64x16
// epi: 0 none, 1: 2x - I (512x512), 2: 2x - extra[b], 3: bias + relu
// ---------------------------------------------------------------------------
__global__ __launch_bounds__(256)
void sgemm_k(int M, int Ncols, int K,
             const float* __restrict__ A, int lda, long sA,
             const float* __restrict__ Bm, int ldb, long sB,
             float* __restrict__ C, int ldc, long sC,
             int epi, const float* __restrict__ extra, long sE,
             const float* __restrict__ bias) {
    __shared__ float As[16][132];
    __shared__ float Bs[16][64];
    int bz = blockIdx.z;
    const float* Ab = A + (long)bz * sA;
    const float* Bb = Bm + (long)bz * sB;
    float* Cb = C + (long)bz * sC;
    int row0 = blockIdx.y * 128, col0 = blockIdx.x * 64;
    int tid = threadIdx.x;
    int tx = tid & 15, ty = tid >> 4;
    float acc[8][4];
    #pragma unroll
    for (int i = 0; i < 8; i++)
        #pragma unroll
        for (int j = 0; j < 4; j++) acc[i][j] = 0.f;
    int am = tid >> 1, ak0 = (tid & 1) << 3;
    int bk = tid >> 4, bn = (tid & 15) << 2;

    for (int k0 = 0; k0 < K; k0 += 16) {
        #pragma unroll
        for (int i = 0; i < 8; i++) {
            int kk = ak0 + i;
            float v = (k0 + kk < K) ? Ab[(long)(row0 + am) * lda + (k0 + kk)] : 0.f;
            As[kk][am] = v;
        }
        #pragma unroll
        for (int i = 0; i < 4; i++) {
            int n = bn + i;
            float v = 0.f;
            if (k0 + bk < K && col0 + n < Ncols) v = Bb[(long)(k0 + bk) * ldb + col0 + n];
            Bs[bk][n] = v;
        }
        __syncthreads();
        #pragma unroll
        for (int kk = 0; kk < 16; kk++) {
            float ar[8], br[4];
            #pragma unroll
            for (int i = 0; i < 8; i++) ar[i] = As[kk][ty * 8 + i];
            #pragma unroll
            for (int j = 0; j < 4; j++) br[j] = Bs[kk][tx * 4 + j];
            #pragma unroll
            for (int i = 0; i < 8; i++)
                #pragma unroll
                for (int j = 0; j < 4; j++) acc[i][j] += ar[i] * br[j];
        }
        __syncthreads();
    }
    #pragma unroll
    for (int i = 0; i < 8; i++) {
        int r = row0 + ty * 8 + i;
        #pragma unroll
        for (int j = 0; j < 4; j++) {
            int c = col0 + tx * 4 + j;
            if (c < Ncols) {
                float v = acc[i][j];
                if (epi == 1) v = 2.f * v - ((r == c) ? 1.f : 0.f);
                else if (epi == 2) v = 2.f * v - extra[(long)bz * sE + (long)r * 512 + c];
                else if (epi == 3) { v += bias[c]; v = v > 0.f ? v : 0.f; }
                Cb[(long)r * ldc + c] = v;
            }
        }
    }
}

// ---------------------------------------------------------------------------
// Contraction GEMM over concatenated diffusion terms.
// A_eff[row=(b,n), k=j*5+m]:
//   m==0: j<fsplit -> X0a[row, j] (ld f); else X0b[row, j-fsplit] (ld 64)
//   m>=1: j<fsplit -> Ta[b, (m-1)*512+n, j] (ld f); else Tb[..., j-fsplit] (ld 64)
// W: (K, Ncols) row-major.  mode 0: gate (sigmoid -> RHX/U), 1: cand (tanh -> GRU)
// ---------------------------------------------------------------------------
__global__ __launch_bounds__(256)
void catgemm_k(int Ncols, int K, int f, int fsplit,
               const float* __restrict__ X0a, const float* __restrict__ X0b,
               const float* __restrict__ Ta, const float* __restrict__ Tb,
               const float* __restrict__ W, const float* __restrict__ bias,
               const float* __restrict__ HX,
               float* __restrict__ RHX, float* __restrict__ Ubuf,
               float* __restrict__ Hout, int mode) {
    __shared__ float As[16][132];
    __shared__ float Bs[16][64];
    int row0 = blockIdx.y * 128, col0 = blockIdx.x * 64;
    int tid = threadIdx.x;
    int tx = tid & 15, ty = tid >> 4;
    float acc[8][4];
    #pragma unroll
    for (int i = 0; i < 8; i++)
        #pragma unroll
        for (int j = 0; j < 4; j++) acc[i][j] = 0.f;
    int am = tid >> 1, ak0 = (tid & 1) << 3;
    int bk = tid >> 4, bn = (tid & 15) << 2;
    int grow_l = row0 + am;
    int b = grow_l >> 9, n = grow_l & 511;

    for (int k0 = 0; k0 < K; k0 += 16) {
        #pragma unroll
        for (int i = 0; i < 8; i++) {
            int k = k0 + ak0 + i;
            float v = 0.f;
            if (k < K) {
                int j = k / 5;
                int m = k - j * 5;
                if (m == 0) {
                    v = (j < fsplit) ? X0a[(long)grow_l * f + j]
                                     : X0b[(long)grow_l * 64 + (j - fsplit)];
                } else {
                    long trow = (long)b * 2048 + (long)(m - 1) * 512 + n;
                    v = (j < fsplit) ? Ta[trow * f + j]
                                     : Tb[trow * 64 + (j - fsplit)];
                }
            }
            As[ak0 + i][am] = v;
        }
        #pragma unroll
        for (int i = 0; i < 4; i++) {
            int c = col0 + bn + i;
            float v = 0.f;
            if (k0 + bk < K && c < Ncols) v = W[(long)(k0 + bk) * Ncols + c];
            Bs[bk][bn + i] = v;
        }
        __syncthreads();
        #pragma unroll
        for (int kk = 0; kk < 16; kk++) {
            float ar[8], br[4];
            #pragma unroll
            for (int i = 0; i < 8; i++) ar[i] = As[kk][ty * 8 + i];
            #pragma unroll
            for (int j = 0; j < 4; j++) br[j] = Bs[kk][tx * 4 + j];
            #pragma unroll
            for (int i = 0; i < 8; i++)
                #pragma unroll
                for (int j = 0; j < 4; j++) acc[i][j] += ar[i] * br[j];
        }
        __syncthreads();
    }
    #pragma unroll
    for (int i = 0; i < 8; i++) {
        int grow = row0 + ty * 8 + i;
        #pragma unroll
        for (int j = 0; j < 4; j++) {
            int c = col0 + tx * 4 + j;
            if (c < Ncols) {
                float v = acc[i][j] + bias[c];
                if (mode == 0) {
                    v = 1.f / (1.f + expf(-v));
                    if (c < 64) RHX[(long)grow * 64 + c] = v * HX[(long)grow * 64 + c];
                    else        Ubuf[(long)grow * 64 + (c - 64)] = v;
                } else {
                    float cc = tanhf(v);
                    float u = Ubuf[(long)grow * 64 + c];
                    float hx = HX[(long)grow * 64 + c];
                    Hout[(long)grow * 64 + c] = u * hx + (1.f - u) * cc;
                }
            }
        }
    }
}

// ---------------------------------------------------------------------------
// Small elementwise kernels
// ---------------------------------------------------------------------------
__global__ void pack_x(float* __restrict__ Xg, int f, int f_in,
                       const float* __restrict__ xin, long sb, int sn,
                       const float* __restrict__ hx, long total) {
    long idx = (long)blockIdx.x * blockDim.x + threadIdx.x;  // over 16384*f
    if (idx >= total) return;
    int c = (int)(idx % f);
    long grow = idx / f;
    int b = (int)(grow >> 9), n = (int)(grow & 511);
    float v;
    if (c < f_in) v = xin[(long)b * sb + (long)n * sn + c];
    else          v = hx[grow * 64 + (c - f_in)];
    Xg[idx] = v;
}

__global__ void add_his_k(float* __restrict__ h0, float* __restrict__ h1,
                          const float* __restrict__ his) {
    int i = blockIdx.x * blockDim.x + threadIdx.x;
    if (i < B_ * N_ * U_) { h0[i] += his[i]; h1[i] += his[i]; }
}

__global__ void proj_k(const float* __restrict__ h, const float* __restrict__ W,
                       const float* __restrict__ bptr, float* __restrict__ decin,
                       float* __restrict__ out, int t) {
    int grow = blockIdx.x * blockDim.x + threadIdx.x;
    if (grow >= B_ * N_) return;
    float s = bptr[0];
    const float* hr = h + (long)grow * 64;
    #pragma unroll
    for (int k = 0; k < 64; k++) s += hr[k] * W[k];
    decin[grow] = s;
    out[(long)grow * HOR + t] = s;
}

// ---------------------------------------------------------------------------
// Host orchestration
// ---------------------------------------------------------------------------
static void sgemm(int M, int Nc, int K,
                  const float* A, int lda, long sA,
                  const float* Bm, int ldb, long sB,
                  float* C, int ldc, long sC, int nb,
                  int epi = 0, const float* extra = nullptr, long sE = 0,
                  const float* bias = nullptr) {
    dim3 g((Nc + 63) / 64, M / 128, nb);
    sgemm_k<<<g, 256>>>(M, Nc, K, A, lda, sA, Bm, ldb, sB, C, ldc, sC, epi, extra, sE, bias);
}

static void cell(float* S, const float* xin, long sb, int sn, int f_in, int f,
                 const float* hx, float* hout,
                 const float* Wg, const float* bg,
                 const float* Wc, const float* bc) {
    float* XG  = S + OFF_XG;
    float* TG  = S + OFF_TG;
    float* TC  = S + OFF_TC;
    float* RHX = S + OFF_RHX;
    float* Ub  = S + OFF_U;
    float* P   = S + OFF_P;

    long nX = (long)B_ * N_ * f;
    pack_x<<<(int)((nX + 255) / 256), 256>>>(XG, f, f_in, xin, sb, sn, hx, nX);
    // Tg = P @ Xg  (all 4 non-identity diffusion terms, all at once)
    sgemm(2048, f, 512, P, 512, (long)4 * N_ * N_, XG, f, (long)N_ * f, TG, f, (long)2048 * f, B_);
    // gate = sigmoid(cat @ Wg + bg); write r*hx and u
    dim3 gg(2, 128, 1);
    catgemm_k<<<gg, 256>>>(128, f * 5, f, f, XG, nullptr, TG, nullptr, Wg, bg, hx,
                           RHX, Ub, nullptr, 0);
    // Tc = P @ (r*hx)
    sgemm(2048, 64, 512, P, 512, (long)4 * N_ * N_, RHX, 64, (long)N_ * 64, TC, 64, (long)2048 * 64, B_);
    // c = tanh(cat_c @ Wc + bc); h = u*hx + (1-u)*c
    dim3 gc(1, 128, 1);
    catgemm_k<<<gc, 256>>>(64, f * 5, f, f_in, XG, RHX, TG, TC, Wc, bc, hx,
                           nullptr, Ub, hout, 1);
}

extern "C" void kernel_launch(void* const* d_in, const int* in_sizes, int n_in,
                              void* d_out, int out_size) {
    (void)in_sizes; (void)n_in; (void)out_size;
    float* S = nullptr;
    cudaGetSymbolAddress((void**)&S, g_scratch);

    const float* hd   = (const float*)d_in[0];   // (32,12,512,2)
    const float* hs   = (const float*)d_in[1];   // (32,512,96)
    const float* adj  = (const float*)d_in[2];   // (32,512,512)
    const float* e0Wg = (const float*)d_in[3];
    const float* e0bg = (const float*)d_in[4];
    const float* e0Wc = (const float*)d_in[5];
    const float* e0bc = (const float*)d_in[6];
    const float* e1Wg = (const float*)d_in[7];
    const float* e1bg = (const float*)d_in[8];
    const float* e1Wc = (const float*)d_in[9];
    const float* e1bc = (const float*)d_in[10];
    const float* d0Wg = (const float*)d_in[11];
    const float* d0bg = (const float*)d_in[12];
    const float* d0Wc = (const float*)d_in[13];
    const float* d0bc = (const float*)d_in[14];
    const float* d1Wg = (const float*)d_in[15];
    const float* d1bg = (const float*)d_in[16];
    const float* d1Wc = (const float*)d_in[17];
    const float* d1bc = (const float*)d_in[18];
    const float* prW  = (const float*)d_in[19];
    const float* prb  = (const float*)d_in[20];
    const float* f1W  = (const float*)d_in[21];
    const float* f1b  = (const float*)d_in[22];
    const float* f2W  = (const float*)d_in[23];
    const float* f2b  = (const float*)d_in[24];
    float* out = (float*)d_out;

    float* A0  = S + OFF_A0;
    float* A1  = S + OFF_A1;
    float* P   = S + OFF_P;
    float* HIS = S + OFF_HIS;
    float* FC1 = S + OFF_FC1;
    float* DEC = S + OFF_DEC;
    float* RS0 = S + OFF_RS0;
    float* RS1 = S + OFF_RS1;
    float* H[4] = {S + OFF_H0, S + OFF_H1, S + OFF_H2, S + OFF_H3};

    const long HSZ = (long)B_ * N_ * U_;
    cudaMemsetAsync(H[0], 0, HSZ * sizeof(float));
    cudaMemsetAsync(H[1], 0, HSZ * sizeof(float));
    cudaMemsetAsync(DEC, 0, (long)B_ * N_ * sizeof(float));

    // ---- supports + stacked diffusion operator P ----
    rowsum_k<<<(B_ * N_ * 32 + 255) / 256, 256>>>(adj, RS0);
    colsum_k<<<(B_ * N_ + 255) / 256, 256>>>(adj, RS1);
    fill_supports<<<(int)(((long)B_ * N_ * N_ + 255) / 256), 256>>>(adj, RS0, RS1, A0, A1, P);
    const long NB = (long)N_ * N_;       // 262144
    const long PB = 4 * NB;              // batch stride of P
    // P block m=2: 2*A0@A0 - I
    sgemm(512, 512, 512, A0, 512, NB, A0, 512, NB, P + NB, 512, PB, B_, 1);
    // P block m=3: A1@A0
    sgemm(512, 512, 512, A1, 512, NB, A0, 512, NB, P + 2 * NB, 512, PB, B_, 0);
    // P block m=4: 2*A1@(A1A0) - A0
    sgemm(512, 512, 512, A1, 512, NB, P + 2 * NB, 512, PB, P + 3 * NB, 512, PB, B_, 2, A0, NB);

    // ---- fc_his (independent of encoder) ----
    sgemm(B_ * N_, 256, 96, hs, 96, 0, f1W, 256, 0, FC1, 256, 0, 1, 3, nullptr, 0, f1b);
    sgemm(B_ * N_, 64, 256, FC1, 256, 0, f2W, 64, 0, HIS, 64, 0, 1, 3, nullptr, 0, f2b);

    float *hc0 = H[0], *hc1 = H[1], *hn0 = H[2], *hn1 = H[3];

    // ---- encoder ----
    for (int t = 0; t < L_; t++) {
        cell(S, hd + (long)t * N_ * 2, (long)L_ * N_ * 2, 2, 2, 66, hc0, hn0, e0Wg, e0bg, e0Wc, e0bc);
        cell(S, hn0, (long)N_ * U_, U_, U_, 128, hc1, hn1, e1Wg, e1bg, e1Wc, e1bc);
        float* tmp;
        tmp = hc0; hc0 = hn0; hn0 = tmp;
        tmp = hc1; hc1 = hn1; hn1 = tmp;
    }
    add_his_k<<<(int)((HSZ + 255) / 256), 256>>>(hc0, hc1, HIS);

    // ---- decoder ----
    for (int t = 0; t < HOR; t++) {
        cell(S, DEC, (long)N_, 1, 1, 65, hc0, hn0, d0Wg, d0bg, d0Wc, d0bc);
        cell(S, hn0, (long)N_ * U_, U_, U_, 128, hc1, hn1, d1Wg, d1bg, d1Wc, d1bc);
        proj_k<<<(B_ * N_ + 255) / 256, 256>>>(hn1, prW, prb, DEC, out, t);
        float* tmp;
        tmp = hc0; hc0 = hn0; hn0 = tmp;
        tmp = hc1; hc1 = hn1; hn1 = tmp;
    }
}

// round 3
// speedup vs baseline: 1.0494x; 1.0494x over previous
#include <cuda_runtime.h>
#include <math.h>

#define B_  32
#define N_  512
#define L_  12
#define U_  64
#define HOR 12

// ---------------------------------------------------------------------------
// Scratch layout (floats)
// ---------------------------------------------------------------------------
constexpr long SZ_NN = (long)B_ * N_ * N_;        // 8388608
constexpr long SZ_T  = (long)B_ * 4 * N_ * U_;    // 4194304  (B, 4*512, 64)
constexpr long SZ_H  = (long)B_ * N_ * U_;        // 1048576

constexpr long OFF_A0   = 0;
constexpr long OFF_A1   = OFF_A0 + SZ_NN;
constexpr long OFF_P    = OFF_A1 + SZ_NN;           // (B, 4*512, 512)
constexpr long OFF_TXIN = OFF_P + 4 * SZ_NN;        // (B, 2048, f_in<=64)
constexpr long OFF_THX  = OFF_TXIN + SZ_T;          // (B, 2048, 64)
constexpr long OFF_TRHX = OFF_THX + SZ_T;           // (B, 2048, 64)
constexpr long OFF_RHX  = OFF_TRHX + SZ_T;
constexpr long OFF_U    = OFF_RHX + SZ_H;
constexpr long OFF_H0   = OFF_U + SZ_H;
constexpr long OFF_H1   = OFF_H0 + SZ_H;
constexpr long OFF_H2   = OFF_H1 + SZ_H;
constexpr long OFF_H3   = OFF_H2 + SZ_H;
constexpr long OFF_HIS  = OFF_H3 + SZ_H;
constexpr long OFF_FC1  = OFF_HIS + SZ_H;           // (16384, 256)
constexpr long OFF_DEC  = OFF_FC1 + (long)B_ * N_ * 256;
constexpr long OFF_RS0  = OFF_DEC + (long)B_ * N_;
constexpr long OFF_RS1  = OFF_RS0 + (long)B_ * N_;
constexpr long SCRATCH_TOTAL = OFF_RS1 + (long)B_ * N_;

__device__ float g_scratch[SCRATCH_TOTAL];

// ---------------------------------------------------------------------------
// Support construction
// ---------------------------------------------------------------------------
__global__ void rowsum_k(const float* __restrict__ adj, float* __restrict__ rs0) {
    int w = (blockIdx.x * blockDim.x + threadIdx.x) >> 5;
    int lane = threadIdx.x & 31;
    if (w >= B_ * N_) return;
    const float* base = adj + (long)w * N_;
    float s = 0.f;
    for (int j = lane; j < N_; j += 32) s += base[j];
    #pragma unroll
    for (int o = 16; o; o >>= 1) s += __shfl_xor_sync(0xffffffffu, s, o);
    if (lane == 0) rs0[w] = s + 1.0f;
}

__global__ void colsum_k(const float* __restrict__ adj, float* __restrict__ rs1) {
    int idx = blockIdx.x * blockDim.x + threadIdx.x;
    if (idx >= B_ * N_) return;
    int b = idx >> 9, i = idx & 511;
    const float* base = adj + (long)b * N_ * N_ + i;
    float s = 1.0f;
    for (int j = 0; j < N_; j++) s += base[(long)j * N_];
    rs1[idx] = s;
}

__global__ void fill_supports(const float* __restrict__ adj,
                              const float* __restrict__ rs0,
                              const float* __restrict__ rs1,
                              float* __restrict__ A0, float* __restrict__ A1,
                              float* __restrict__ P) {
    long idx = (long)blockIdx.x * blockDim.x + threadIdx.x;
    if (idx >= (long)B_ * N_ * N_) return;
    int j = (int)(idx & 511);
    long t = idx >> 9;
    int i = (int)(t & 511);
    int b = (int)(t >> 9);
    float d = (i == j) ? 1.f : 0.f;
    float a = adj[idx];
    float v0 = (a + d) / rs0[b * N_ + i];
    A0[idx] = v0;
    P[(long)b * 4 * N_ * N_ + (long)i * N_ + j] = v0;   // block m=1: A0
    float at = adj[((long)b * N_ + j) * N_ + i];
    A1[idx] = (at + d) / rs1[b * N_ + i];
}

// ---------------------------------------------------------------------------
// Batched SGEMM, double-buffered, float4 paths.
//   C[b] = A[b] @ B[b] (row-major). Requires: gridDim.y*BM == M rows used,
//   Ncols multiple of BN (no col guards), K arbitrary (guarded).
// epi: 0 none, 1: 2x - I, 2: 2x - extra[b], 3: bias + relu
// ---------------------------------------------------------------------------
template<int BM, int BN, int TM, int TN>
__global__ __launch_bounds__(256, 2)
void sgemm_t(int K,
             const float* __restrict__ A, int lda, long sA,
             const float* __restrict__ Bm, int ldb, long sB,
             float* __restrict__ C, int ldc, long sC,
             int epi, const float* __restrict__ extra, long sE,
             const float* __restrict__ bias)
{
    constexpr int BK = 16;
    constexpr int TX = BN / TN;
    constexpr int AF = BM / 64;
    constexpr int BF = BN / 64;
    __shared__ float As[2][BK][BM + 4];
    __shared__ float Bs[2][BK][BN];
    int bz = blockIdx.z;
    const float* Ab = A + (long)bz * sA;
    const float* Bb = Bm + (long)bz * sB;
    float* Cb = C + (long)bz * sC;
    int row0 = blockIdx.y * BM, col0 = blockIdx.x * BN;
    int tid = threadIdx.x;
    int tx = tid % TX, ty = tid / TX;

    int aRow[AF], aCol[AF], bRow[BF], bCol[BF];
    #pragma unroll
    for (int s = 0; s < AF; s++) { int idx = tid + s * 256; aRow[s] = idx >> 2; aCol[s] = (idx & 3) << 2; }
    #pragma unroll
    for (int s = 0; s < BF; s++) { int idx = tid + s * 256; bRow[s] = idx / (BN / 4); bCol[s] = (idx % (BN / 4)) << 2; }

    float4 aR[AF], bR[BF];

    auto ldT = [&](int k0) {
        #pragma unroll
        for (int s = 0; s < AF; s++) {
            const float* p = Ab + (long)(row0 + aRow[s]) * lda + k0 + aCol[s];
            if (k0 + BK <= K) aR[s] = *(const float4*)p;
            else {
                int k = k0 + aCol[s];
                aR[s].x = (k     < K) ? p[0] : 0.f;
                aR[s].y = (k + 1 < K) ? p[1] : 0.f;
                aR[s].z = (k + 2 < K) ? p[2] : 0.f;
                aR[s].w = (k + 3 < K) ? p[3] : 0.f;
            }
        }
        #pragma unroll
        for (int s = 0; s < BF; s++) {
            int k = k0 + bRow[s];
            if (k < K) bR[s] = *(const float4*)(Bb + (long)k * ldb + col0 + bCol[s]);
            else bR[s] = make_float4(0.f, 0.f, 0.f, 0.f);
        }
    };
    auto stT = [&](int buf) {
        #pragma unroll
        for (int s = 0; s < AF; s++) {
            As[buf][aCol[s]    ][aRow[s]] = aR[s].x;
            As[buf][aCol[s] + 1][aRow[s]] = aR[s].y;
            As[buf][aCol[s] + 2][aRow[s]] = aR[s].z;
            As[buf][aCol[s] + 3][aRow[s]] = aR[s].w;
        }
        #pragma unroll
        for (int s = 0; s < BF; s++)
            *(float4*)&Bs[buf][bRow[s]][bCol[s]] = bR[s];
    };

    float acc[TM][TN];
    #pragma unroll
    for (int i = 0; i < TM; i++)
        #pragma unroll
        for (int j = 0; j < TN; j++) acc[i][j] = 0.f;

    int ntile = (K + BK - 1) / BK;
    ldT(0); stT(0); __syncthreads();
    for (int t = 0; t < ntile; t++) {
        if (t + 1 < ntile) ldT((t + 1) * BK);
        int buf = t & 1;
        #pragma unroll
        for (int kk = 0; kk < BK; kk++) {
            float ar[TM], br[TN];
            #pragma unroll
            for (int i = 0; i < TM / 4; i++)
                *(float4*)&ar[i * 4] = *(const float4*)&As[buf][kk][ty * TM + i * 4];
            #pragma unroll
            for (int j = 0; j < TN / 4; j++)
                *(float4*)&br[j * 4] = *(const float4*)&Bs[buf][kk][tx * TN + j * 4];
            #pragma unroll
            for (int i = 0; i < TM; i++)
                #pragma unroll
                for (int j = 0; j < TN; j++) acc[i][j] += ar[i] * br[j];
        }
        if (t + 1 < ntile) stT(buf ^ 1);
        __syncthreads();
    }

    #pragma unroll
    for (int i = 0; i < TM; i++) {
        int r = row0 + ty * TM + i;
        #pragma unroll
        for (int j = 0; j < TN; j++) {
            int c = col0 + tx * TN + j;
            float v = acc[i][j];
            if (epi == 1) v = 2.f * v - ((r == c) ? 1.f : 0.f);
            else if (epi == 2) v = 2.f * v - extra[(long)bz * sE + (long)r * N_ + c];
            else if (epi == 3) { v += bias[c]; v = fmaxf(v, 0.f); }
            Cb[(long)r * ldc + c] = v;
        }
    }
}

// ---------------------------------------------------------------------------
// Contraction GEMM over virtual concatenated diffusion terms (no packed X).
// A_eff[row=(b,n), k=j*5+m]:
//   m==0: j<f_in -> Xa[b*sb + n*sn + j]          else Xb[row*64 + j-f_in]
//   m>=1: j<f_in -> Ta[(b*2048+(m-1)*512+n)*f_in + j]
//                   else Tb[(b*2048+(m-1)*512+n)*64 + j-f_in]
// mode 0: gate (sigmoid -> RHX/U, Ncols=128). mode 1: cand (tanh -> GRU, Ncols=64)
// ---------------------------------------------------------------------------
template<int BN, int TN>
__global__ __launch_bounds__(256, 2)
void catgemm_t(int K, int f_in,
               const float* __restrict__ Xa, long sb, int sn,
               const float* __restrict__ Xb,
               const float* __restrict__ Ta,
               const float* __restrict__ Tb,
               const float* __restrict__ W, const float* __restrict__ bias,
               const float* __restrict__ HX,
               float* __restrict__ RHX, float* __restrict__ Ubuf,
               float* __restrict__ Hout, int mode)
{
    constexpr int BM = 128, TM = 8, BK = 16;
    constexpr int BF = BN / 64;
    __shared__ float As[2][BK][BM + 4];
    __shared__ float Bs[2][BK][BN];
    int row0 = blockIdx.y * BM;
    int col0 = blockIdx.x * BN;
    int tid = threadIdx.x;
    int tx = tid % 16, ty = tid / 16;
    int am = tid >> 1, ak0 = (tid & 1) << 3;
    int growL = row0 + am;
    int bL = growL >> 9, nL = growL & 511;

    int bRow[BF], bCol[BF];
    #pragma unroll
    for (int s = 0; s < BF; s++) { int idx = tid + s * 256; bRow[s] = idx / (BN / 4); bCol[s] = (idx % (BN / 4)) << 2; }

    float aR[8];
    float4 bR[BF];

    auto ldT = [&](int k0) {
        #pragma unroll
        for (int i = 0; i < 8; i++) {
            int k = k0 + ak0 + i;
            float v = 0.f;
            if (k < K) {
                int j = k / 5;
                int m = k - j * 5;
                if (m == 0) {
                    v = (j < f_in) ? Xa[(long)bL * sb + (long)nL * sn + j]
                                   : Xb[(long)growL * 64 + (j - f_in)];
                } else {
                    long trow = (long)bL * 2048 + (long)(m - 1) * 512 + nL;
                    v = (j < f_in) ? Ta[trow * f_in + j]
                                   : Tb[trow * 64 + (j - f_in)];
                }
            }
            aR[i] = v;
        }
        #pragma unroll
        for (int s = 0; s < BF; s++) {
            int k = k0 + bRow[s];
            if (k < K) bR[s] = *(const float4*)(W + (long)k * BN * gridDim.x + col0 + bCol[s]);
            else bR[s] = make_float4(0.f, 0.f, 0.f, 0.f);
        }
    };
    auto stT = [&](int buf) {
        #pragma unroll
        for (int i = 0; i < 8; i++) As[buf][ak0 + i][am] = aR[i];
        #pragma unroll
        for (int s = 0; s < BF; s++) *(float4*)&Bs[buf][bRow[s]][bCol[s]] = bR[s];
    };

    float acc[TM][TN];
    #pragma unroll
    for (int i = 0; i < TM; i++)
        #pragma unroll
        for (int j = 0; j < TN; j++) acc[i][j] = 0.f;

    int ntile = (K + BK - 1) / BK;
    ldT(0); stT(0); __syncthreads();
    for (int t = 0; t < ntile; t++) {
        if (t + 1 < ntile) ldT((t + 1) * BK);
        int buf = t & 1;
        #pragma unroll
        for (int kk = 0; kk < BK; kk++) {
            float ar[TM], br[TN];
            #pragma unroll
            for (int i = 0; i < TM / 4; i++)
                *(float4*)&ar[i * 4] = *(const float4*)&As[buf][kk][ty * TM + i * 4];
            #pragma unroll
            for (int j = 0; j < TN / 4; j++)
                *(float4*)&br[j * 4] = *(const float4*)&Bs[buf][kk][tx * TN + j * 4];
            #pragma unroll
            for (int i = 0; i < TM; i++)
                #pragma unroll
                for (int j = 0; j < TN; j++) acc[i][j] += ar[i] * br[j];
        }
        if (t + 1 < ntile) stT(buf ^ 1);
        __syncthreads();
    }

    #pragma unroll
    for (int i = 0; i < TM; i++) {
        int grow = row0 + ty * TM + i;
        #pragma unroll
        for (int j = 0; j < TN; j++) {
            int c = col0 + tx * TN + j;
            float v = acc[i][j] + bias[c];
            if (mode == 0) {
                v = 1.f / (1.f + expf(-v));
                if (c < 64) RHX[(long)grow * 64 + c] = v * HX[(long)grow * 64 + c];
                else        Ubuf[(long)grow * 64 + (c - 64)] = v;
            } else {
                float cc = tanhf(v);
                float u = Ubuf[(long)grow * 64 + c];
                float hx = HX[(long)grow * 64 + c];
                Hout[(long)grow * 64 + c] = u * hx + (1.f - u) * cc;
            }
        }
    }
}

// ---------------------------------------------------------------------------
// Thin diffusion: T[b, r, c] = sum_j P[b, r, j] * xin[b, j, c], f_in in {1,2}
// one warp per output row
// ---------------------------------------------------------------------------
__global__ void thin_apply_k(const float* __restrict__ P,
                             const float* __restrict__ xin, long sb, int sn, int f_in,
                             float* __restrict__ T) {
    int gw = (blockIdx.x * blockDim.x + threadIdx.x) >> 5;
    int lane = threadIdx.x & 31;
    if (gw >= B_ * 2048) return;
    int b = gw >> 11, r = gw & 2047;
    const float* Prow = P + ((long)b * 2048 + r) * 512;
    const float* xb = xin + (long)b * sb;
    float a0 = 0.f, a1 = 0.f;
    for (int j = lane; j < 512; j += 32) {
        float p = Prow[j];
        a0 += p * xb[(long)j * sn];
        if (f_in == 2) a1 += p * xb[(long)j * sn + 1];
    }
    #pragma unroll
    for (int o = 16; o; o >>= 1) {
        a0 += __shfl_xor_sync(0xffffffffu, a0, o);
        a1 += __shfl_xor_sync(0xffffffffu, a1, o);
    }
    if (lane == 0) {
        T[(long)gw * f_in] = a0;
        if (f_in == 2) T[(long)gw * f_in + 1] = a1;
    }
}

// ---------------------------------------------------------------------------
// Misc small kernels
// ---------------------------------------------------------------------------
__global__ void add_his_k(float* __restrict__ h0, float* __restrict__ h1,
                          const float* __restrict__ his) {
    int i = blockIdx.x * blockDim.x + threadIdx.x;
    if (i < B_ * N_ * U_) { h0[i] += his[i]; h1[i] += his[i]; }
}

__global__ void proj_k(const float* __restrict__ h, const float* __restrict__ W,
                       const float* __restrict__ bptr, float* __restrict__ decin,
                       float* __restrict__ out, int t) {
    int grow = blockIdx.x * blockDim.x + threadIdx.x;
    if (grow >= B_ * N_) return;
    float s = bptr[0];
    const float* hr = h + (long)grow * 64;
    #pragma unroll
    for (int k = 0; k < 64; k++) s += hr[k] * W[k];
    decin[grow] = s;
    out[(long)grow * HOR + t] = s;
}

// ---------------------------------------------------------------------------
// Host orchestration
// ---------------------------------------------------------------------------
static void apply64(const float* P, const float* X, long sX, float* T) {
    // T[b](2048 x 64) = P[b](2048 x 512) @ X[b](512 x 64)
    dim3 g(1, 8, B_);
    sgemm_t<256, 64, 16, 4><<<g, 256>>>(512, P, 512, (long)4 * N_ * N_,
                                        X, 64, sX, T, 64, (long)2048 * 64,
                                        0, nullptr, 0, nullptr);
}

static void cell(float* S, const float* xin, long sb, int sn, int f_in,
                 const float* hx, float* hout,
                 const float* Wg, const float* bg,
                 const float* Wc, const float* bc) {
    float* P    = S + OFF_P;
    float* TXIN = S + OFF_TXIN;
    float* THX  = S + OFF_THX;
    float* TRHX = S + OFF_TRHX;
    float* RHX  = S + OFF_RHX;
    float* Ub   = S + OFF_U;

    if (f_in == 64) apply64(P, xin, sb, TXIN);
    else thin_apply_k<<<8192, 256>>>(P, xin, sb, sn, f_in, TXIN);
    apply64(P, hx, (long)N_ * 64, THX);
    int K = (f_in + 64) * 5;
    catgemm_t<128, 8><<<dim3(1, 128), 256>>>(K, f_in, xin, sb, sn, hx, TXIN, THX,
                                             Wg, bg, hx, RHX, Ub, nullptr, 0);
    apply64(P, RHX, (long)N_ * 64, TRHX);
    catgemm_t<64, 4><<<dim3(1, 128), 256>>>(K, f_in, xin, sb, sn, RHX, TXIN, TRHX,
                                            Wc, bc, hx, nullptr, Ub, hout, 1);
}

extern "C" void kernel_launch(void* const* d_in, const int* in_sizes, int n_in,
                              void* d_out, int out_size) {
    (void)in_sizes; (void)n_in; (void)out_size;
    float* S = nullptr;
    cudaGetSymbolAddress((void**)&S, g_scratch);

    const float* hd   = (const float*)d_in[0];
    const float* hs   = (const float*)d_in[1];
    const float* adj  = (const float*)d_in[2];
    const float* e0Wg = (const float*)d_in[3];
    const float* e0bg = (const float*)d_in[4];
    const float* e0Wc = (const float*)d_in[5];
    const float* e0bc = (const float*)d_in[6];
    const float* e1Wg = (const float*)d_in[7];
    const float* e1bg = (const float*)d_in[8];
    const float* e1Wc = (const float*)d_in[9];
    const float* e1bc = (const float*)d_in[10];
    const float* d0Wg = (const float*)d_in[11];
    const float* d0bg = (const float*)d_in[12];
    const float* d0Wc = (const float*)d_in[13];
    const float* d0bc = (const float*)d_in[14];
    const float* d1Wg = (const float*)d_in[15];
    const float* d1bg = (const float*)d_in[16];
    const float* d1Wc = (const float*)d_in[17];
    const float* d1bc = (const float*)d_in[18];
    const float* prW  = (const float*)d_in[19];
    const float* prb  = (const float*)d_in[20];
    const float* f1W  = (const float*)d_in[21];
    const float* f1b  = (const float*)d_in[22];
    const float* f2W  = (const float*)d_in[23];
    const float* f2b  = (const float*)d_in[24];
    float* out = (float*)d_out;

    float* A0  = S + OFF_A0;
    float* A1  = S + OFF_A1;
    float* P   = S + OFF_P;
    float* HIS = S + OFF_HIS;
    float* FC1 = S + OFF_FC1;
    float* DEC = S + OFF_DEC;
    float* RS0 = S + OFF_RS0;
    float* RS1 = S + OFF_RS1;
    float* H[4] = {S + OFF_H0, S + OFF_H1, S + OFF_H2, S + OFF_H3};

    const long HSZ = (long)B_ * N_ * U_;
    cudaMemsetAsync(H[0], 0, HSZ * sizeof(float));
    cudaMemsetAsync(H[1], 0, HSZ * sizeof(float));
    cudaMemsetAsync(DEC, 0, (long)B_ * N_ * sizeof(float));

    // ---- supports + stacked diffusion operator P ----
    rowsum_k<<<(B_ * N_ * 32 + 255) / 256, 256>>>(adj, RS0);
    colsum_k<<<(B_ * N_ + 255) / 256, 256>>>(adj, RS1);
    fill_supports<<<(int)(((long)B_ * N_ * N_ + 255) / 256), 256>>>(adj, RS0, RS1, A0, A1, P);
    const long NB = (long)N_ * N_;
    const long PB = 4 * NB;
    dim3 gp(4, 4, B_);
    // P block m=2: 2*A0@A0 - I
    sgemm_t<128, 128, 8, 8><<<gp, 256>>>(512, A0, 512, NB, A0, 512, NB,
                                         P + NB, 512, PB, 1, nullptr, 0, nullptr);
    // P block m=3: A1@A0
    sgemm_t<128, 128, 8, 8><<<gp, 256>>>(512, A1, 512, NB, A0, 512, NB,
                                         P + 2 * NB, 512, PB, 0, nullptr, 0, nullptr);
    // P block m=4: 2*A1@(A1A0) - A0
    sgemm_t<128, 128, 8, 8><<<gp, 256>>>(512, A1, 512, NB, P + 2 * NB, 512, PB,
                                         P + 3 * NB, 512, PB, 2, A0, NB, nullptr);

    // ---- fc_his ----
    sgemm_t<128, 128, 8, 8><<<dim3(2, 128, 1), 256>>>(96, hs, 96, 0, f1W, 256, 0,
                                                      FC1, 256, 0, 3, nullptr, 0, f1b);
    sgemm_t<256, 64, 16, 4><<<dim3(1, 64, 1), 256>>>(256, FC1, 256, 0, f2W, 64, 0,
                                                     HIS, 64, 0, 3, nullptr, 0, f2b);

    float *hc0 = H[0], *hc1 = H[1], *hn0 = H[2], *hn1 = H[3];

    // ---- encoder ----
    for (int t = 0; t < L_; t++) {
        cell(S, hd + (long)t * N_ * 2, (long)L_ * N_ * 2, 2, 2, hc0, hn0, e0Wg, e0bg, e0Wc, e0bc);
        cell(S, hn0, (long)N_ * U_, U_, 64, hc1, hn1, e1Wg, e1bg, e1Wc, e1bc);
        float* tmp;
        tmp = hc0; hc0 = hn0; hn0 = tmp;
        tmp = hc1; hc1 = hn1; hn1 = tmp;
    }
    add_his_k<<<(int)((HSZ + 255) / 256), 256>>>(hc0, hc1, HIS);

    // ---- decoder ----
    for (int t = 0; t < HOR; t++) {
        cell(S, DEC, (long)N_, 1, 1, hc0, hn0, d0Wg, d0bg, d0Wc, d0bc);
        cell(S, hn0, (long)N_ * U_, U_, 64, hc1, hn1, d1Wg, d1bg, d1Wc, d1bc);
        proj_k<<<(B_ * N_ + 255) / 256, 256>>>(hn1, prW, prb, DEC, out, t);
        float* tmp;
        tmp = hc0; hc0 = hn0; hn0 = tmp;
        tmp = hc1; hc1 = hn1; hn1 = tmp;
    }
}